// round 1
// baseline (speedup 1.0000x reference)
#include <cuda_runtime.h>
#include <stdint.h>

// Problem constants (fixed shapes from reference): x = (32, 3, 512, 512) f32.
// 96 images, 8x8 tile grid, tiles of 64x64 (area 4096), 256 bins, clip=32.
#define N_IMG      96
#define IMG_H      512
#define IMG_W      512
#define IMG_PIX    (IMG_H * IMG_W)          // 262144
#define GRID_G     8
#define TILE_H     64
#define TILE_W     64
#define TILE_AREA  (TILE_H * TILE_W)        // 4096
#define NBINS      256
#define CLIP_V     32
#define N_TILES    (N_IMG * GRID_G * GRID_G) // 6144

// Scratch: quantized u8 image + per-tile LUTs (u8). __device__ globals (no alloc).
__device__ uint8_t g_img[(size_t)N_IMG * IMG_PIX];        // 24 MiB
__device__ uint8_t g_lut[(size_t)N_TILES * NBINS];        // 1.5 MiB

// ---------------------------------------------------------------------------
// Kernel 1: per-tile histogram -> clip -> redistribute -> cdf -> LUT,
// and quantize the image to u8 scratch on the way through.
// One block (256 threads) per tile. Each thread: 4 float4 loads (16 px).
// ---------------------------------------------------------------------------
__global__ void __launch_bounds__(256)
clahe_hist_lut_kernel(const float* __restrict__ x)
{
    const int tid     = threadIdx.x;        // 0..255, also "my bin"
    const int tile_id = blockIdx.x;         // 0..6143
    const int bc      = tile_id >> 6;       // image index
    const int t       = tile_id & 63;
    const int gy      = t >> 3;
    const int gx      = t & 7;

    __shared__ int s_hist[NBINS];
    __shared__ int s_excess;
    __shared__ int s_warp[8];

    s_hist[tid] = 0;
    if (tid == 0) s_excess = 0;
    __syncthreads();

    const float* img  = x + (size_t)bc * IMG_PIX;
    uint8_t*     dimg = g_img + (size_t)bc * IMG_PIX;

    const int row0 = gy * TILE_H;
    const int col0 = gx * TILE_W;

    #pragma unroll
    for (int i = 0; i < 4; i++) {
        int q  = tid + i * 256;             // float4 index within tile: 0..1023
        int r  = q >> 4;                    // tile row (16 float4 per 64-px row)
        int c4 = q & 15;
        size_t off = (size_t)(row0 + r) * IMG_W + col0 + c4 * 4;
        float4 v = *(const float4*)(img + off);
        // match jnp.round (round-half-even) of clip(x,0,1)*255
        unsigned p0 = (unsigned)rintf(__saturatef(v.x) * 255.0f);
        unsigned p1 = (unsigned)rintf(__saturatef(v.y) * 255.0f);
        unsigned p2 = (unsigned)rintf(__saturatef(v.z) * 255.0f);
        unsigned p3 = (unsigned)rintf(__saturatef(v.w) * 255.0f);
        atomicAdd(&s_hist[p0], 1);
        atomicAdd(&s_hist[p1], 1);
        atomicAdd(&s_hist[p2], 1);
        atomicAdd(&s_hist[p3], 1);
        unsigned packed = p0 | (p1 << 8) | (p2 << 16) | (p3 << 24);
        *(unsigned*)(dimg + off) = packed;
    }
    __syncthreads();

    // clip + excess reduction
    int h       = s_hist[tid];
    int clipped = min(h, CLIP_V);
    int over    = h - clipped;
    #pragma unroll
    for (int o = 16; o > 0; o >>= 1)
        over += __shfl_down_sync(0xffffffffu, over, o);
    if ((tid & 31) == 0) atomicAdd(&s_excess, over);
    __syncthreads();

    const int excess    = s_excess;
    const int batch_add = excess >> 8;           // excess / 256
    const int residual  = excess & 255;          // excess % 256
    const int step      = max(256 / max(residual, 1), 1);
    const int extra     = ((tid % step) == 0 && (tid / step) < residual) ? 1 : 0;
    int v = clipped + batch_add + extra;

    // inclusive scan over 256 bins (warp scan + warp-sum scan)
    const int lane = tid & 31, wid = tid >> 5;
    int sv = v;
    #pragma unroll
    for (int o = 1; o < 32; o <<= 1) {
        int n = __shfl_up_sync(0xffffffffu, sv, o);
        if (lane >= o) sv += n;
    }
    if (lane == 31) s_warp[wid] = sv;
    __syncthreads();
    if (wid == 0 && lane < 8) {
        int w = s_warp[lane];
        #pragma unroll
        for (int o = 1; o < 8; o <<= 1) {
            int n = __shfl_up_sync(0x000000ffu, w, o);
            if (lane >= o) w += n;
        }
        s_warp[lane] = w;
    }
    __syncthreads();
    int cdf = sv + (wid ? s_warp[wid - 1] : 0);   // 1..4096

    // lut = clip(round(cdf * 255/4096), 0, 255); exact in f32, rintf = half-even
    float lf = rintf((float)cdf * (255.0f / 4096.0f));
    int   li = min(max((int)lf, 0), 255);
    g_lut[(size_t)tile_id * NBINS + tid] = (uint8_t)li;
}

// ---------------------------------------------------------------------------
// Kernel 2: apply LUTs with bilinear tile interpolation.
// One block (256 threads) per 32-row band of one image (16 bands/img).
// Each band needs exactly two tile-rows of LUTs -> 4 KB staged in shared.
// ---------------------------------------------------------------------------
__global__ void __launch_bounds__(256)
clahe_apply_kernel(float* __restrict__ out)
{
    const int tid  = threadIdx.x;
    const int blk  = blockIdx.x;        // 0 .. 96*16-1
    const int bc   = blk >> 4;
    const int band = blk & 15;
    const int y0   = band * 32;

    // tile-row indices for this band (i1 unclamped first, like reference)
    const int i1u = (band - 1) >> 1;            // floor((band-1)/2), -1 at band 0
    const int ty1 = max(i1u, 0);
    const int ty2 = min(i1u + 1, GRID_G - 1);

    __shared__ uint8_t s_lut[2][GRID_G * NBINS];   // 2 x 2048 B
    __shared__ float   s_outv[256];                // k -> round-exact k/255.0f

    // stage the two LUT rows (2048 B each) with uint4 copies
    {
        const uint4* lutA = (const uint4*)(g_lut + ((size_t)(bc * GRID_G + ty1) * GRID_G) * NBINS);
        const uint4* lutB = (const uint4*)(g_lut + ((size_t)(bc * GRID_G + ty2) * GRID_G) * NBINS);
        if (tid < 128) ((uint4*)s_lut[0])[tid] = lutA[tid];
        else           ((uint4*)s_lut[1])[tid - 128] = lutB[tid - 128];
    }
    // exact IEEE division table: out value = round(res)/255.0
    s_outv[tid] = __fdiv_rn((float)tid, 255.0f);
    __syncthreads();

    const uint8_t* dimg = g_img + (size_t)bc * IMG_PIX + (size_t)y0 * IMG_W;
    float*         o    = out   + (size_t)bc * IMG_PIX + (size_t)y0 * IMG_W;

    #pragma unroll
    for (int it = 0; it < 16; it++) {
        int q  = tid + it * 256;        // u32 (4-pixel) index in band: 0..4095
        int r  = q >> 7;                // row in band 0..31
        int c4 = q & 127;
        int y  = y0 + r;

        float fy  = (float)y * 0.015625f - 0.5f;
        float fyl = floorf(fy);
        float ya  = fy - fyl;
        float wy1 = 1.0f - ya;
        float wy2 = ya;

        unsigned p = *(const unsigned*)(dimg + (size_t)r * IMG_W + c4 * 4);

        float4 res;
        float* rp = (float*)&res;
        #pragma unroll
        for (int j = 0; j < 4; j++) {
            int   xx  = c4 * 4 + j;
            float fx  = (float)xx * 0.015625f - 0.5f;
            float fxl = floorf(fx);
            float xa  = fx - fxl;
            int   i1  = (int)fxl;
            int   tx2 = min(i1 + 1, GRID_G - 1);
            int   tx1 = max(i1, 0);
            float wx1 = 1.0f - xa;
            float wx2 = xa;

            int v = (p >> (8 * j)) & 255;
            float l11 = (float)s_lut[0][tx1 * NBINS + v];
            float l12 = (float)s_lut[0][tx2 * NBINS + v];
            float l21 = (float)s_lut[1][tx1 * NBINS + v];
            float l22 = (float)s_lut[1][tx2 * NBINS + v];

            // exact in f32: all terms are m/4096 with m < 2^24
            float rr = l11 * (wy1 * wx1) + l12 * (wy1 * wx2)
                     + l21 * (wy2 * wx1) + l22 * (wy2 * wx2);
            int k = min(max((int)rintf(rr), 0), 255);
            rp[j] = s_outv[k];
        }
        *(float4*)(o + (size_t)r * IMG_W + c4 * 4) = res;
    }
}

// ---------------------------------------------------------------------------
extern "C" void kernel_launch(void* const* d_in, const int* in_sizes, int n_in,
                              void* d_out, int out_size)
{
    const float* x   = (const float*)d_in[0];
    float*       out = (float*)d_out;
    (void)in_sizes; (void)n_in; (void)out_size;

    clahe_hist_lut_kernel<<<N_TILES, 256>>>(x);
    clahe_apply_kernel<<<N_IMG * 16, 256>>>(out);
}

// round 2
// speedup vs baseline: 1.2913x; 1.2913x over previous
#include <cuda_runtime.h>
#include <stdint.h>

// Problem constants (fixed shapes from reference): x = (32, 3, 512, 512) f32.
// 96 images, 8x8 tile grid, tiles of 64x64 (area 4096), 256 bins, clip=32.
#define N_IMG      96
#define IMG_H      512
#define IMG_W      512
#define IMG_PIX    (IMG_H * IMG_W)          // 262144
#define GRID_G     8
#define TILE_H     64
#define TILE_W     64
#define TILE_AREA  (TILE_H * TILE_W)        // 4096
#define NBINS      256
#define CLIP_V     32
#define N_TILES    (N_IMG * GRID_G * GRID_G) // 6144

// Scratch: quantized u8 image + per-tile LUTs (u8). __device__ globals (no alloc).
__device__ uint8_t g_img[(size_t)N_IMG * IMG_PIX];        // 24 MiB
__device__ uint8_t g_lut[(size_t)N_TILES * NBINS];        // 1.5 MiB

// ---------------------------------------------------------------------------
// Kernel 1: per-tile histogram -> clip -> redistribute -> cdf -> LUT,
// and quantize the image to u8 scratch on the way through.
// One block (256 threads) per tile. Each thread: 4 float4 loads (16 px).
// ---------------------------------------------------------------------------
__global__ void __launch_bounds__(256)
clahe_hist_lut_kernel(const float* __restrict__ x)
{
    const int tid     = threadIdx.x;        // 0..255, also "my bin"
    const int tile_id = blockIdx.x;         // 0..6143
    const int bc      = tile_id >> 6;       // image index
    const int t       = tile_id & 63;
    const int gy      = t >> 3;
    const int gx      = t & 7;

    __shared__ int s_hist[NBINS];
    __shared__ int s_excess;
    __shared__ int s_warp[8];

    s_hist[tid] = 0;
    if (tid == 0) s_excess = 0;
    __syncthreads();

    const float* img  = x + (size_t)bc * IMG_PIX;
    uint8_t*     dimg = g_img + (size_t)bc * IMG_PIX;

    const int row0 = gy * TILE_H;
    const int col0 = gx * TILE_W;

    #pragma unroll
    for (int i = 0; i < 4; i++) {
        int q  = tid + i * 256;             // float4 index within tile: 0..1023
        int r  = q >> 4;                    // tile row (16 float4 per 64-px row)
        int c4 = q & 15;
        size_t off = (size_t)(row0 + r) * IMG_W + col0 + c4 * 4;
        float4 v = *(const float4*)(img + off);
        // match jnp.round (round-half-even) of clip(x,0,1)*255
        unsigned p0 = (unsigned)rintf(__saturatef(v.x) * 255.0f);
        unsigned p1 = (unsigned)rintf(__saturatef(v.y) * 255.0f);
        unsigned p2 = (unsigned)rintf(__saturatef(v.z) * 255.0f);
        unsigned p3 = (unsigned)rintf(__saturatef(v.w) * 255.0f);
        atomicAdd(&s_hist[p0], 1);
        atomicAdd(&s_hist[p1], 1);
        atomicAdd(&s_hist[p2], 1);
        atomicAdd(&s_hist[p3], 1);
        unsigned packed = p0 | (p1 << 8) | (p2 << 16) | (p3 << 24);
        *(unsigned*)(dimg + off) = packed;
    }
    __syncthreads();

    // clip + excess reduction
    int h       = s_hist[tid];
    int clipped = min(h, CLIP_V);
    int over    = h - clipped;
    #pragma unroll
    for (int o = 16; o > 0; o >>= 1)
        over += __shfl_down_sync(0xffffffffu, over, o);
    if ((tid & 31) == 0) atomicAdd(&s_excess, over);
    __syncthreads();

    const int excess    = s_excess;
    const int batch_add = excess >> 8;           // excess / 256
    const int residual  = excess & 255;          // excess % 256
    const int step      = max(256 / max(residual, 1), 1);
    const int extra     = ((tid % step) == 0 && (tid / step) < residual) ? 1 : 0;
    int v = clipped + batch_add + extra;

    // inclusive scan over 256 bins (warp scan + warp-sum scan)
    const int lane = tid & 31, wid = tid >> 5;
    int sv = v;
    #pragma unroll
    for (int o = 1; o < 32; o <<= 1) {
        int n = __shfl_up_sync(0xffffffffu, sv, o);
        if (lane >= o) sv += n;
    }
    if (lane == 31) s_warp[wid] = sv;
    __syncthreads();
    if (wid == 0 && lane < 8) {
        int w = s_warp[lane];
        #pragma unroll
        for (int o = 1; o < 8; o <<= 1) {
            int n = __shfl_up_sync(0x000000ffu, w, o);
            if (lane >= o) w += n;
        }
        s_warp[lane] = w;
    }
    __syncthreads();
    int cdf = sv + (wid ? s_warp[wid - 1] : 0);   // 1..4096

    // lut = clip(round(cdf * 255/4096), 0, 255); exact in f32, rintf = half-even
    float lf = rintf((float)cdf * (255.0f / 4096.0f));
    int   li = min(max((int)lf, 0), 255);
    g_lut[(size_t)tile_id * NBINS + tid] = (uint8_t)li;
}

// ---------------------------------------------------------------------------
// Kernel 2: apply LUTs with bilinear tile interpolation.
// One block (256 threads) per 32-row band of one image (16 bands/img).
// Each band needs exactly two tile-rows of LUTs. We prebuild a fused table:
//   s_comb[pair][v] = l11 | l12<<8 | l21<<16 | l22<<24
// for the 9 distinct tile-column pairs, so each pixel needs ONE u32 LDS
// (instead of 4 byte gathers) + exact integer DP4A bilinear + 1 outv LDS.
//
// Exactness: reference computes res = sum l*(w) where every weight is
// m/4096 (m<=4096) and every product/sum is an exact f32 multiple of 1/4096
// below 2^24, so res == N/4096 with integer
//   N = dp4a row-interp (weights <=64) combined with iay weights.
// round-half-even of N/4096 in integer: k = (N + 2047 + ((N>>12)&1)) >> 12.
// ---------------------------------------------------------------------------
__global__ void __launch_bounds__(256)
clahe_apply_kernel(float* __restrict__ out)
{
    const int tid  = threadIdx.x;
    const int blk  = blockIdx.x;        // 0 .. 96*16-1
    const int bc   = blk >> 4;
    const int band = blk & 15;
    const int y0   = band * 32;

    // tile-row indices for this band (i1 unclamped first, like reference)
    const int i1u = (band - 1) >> 1;            // floor((band-1)/2), -1 at band 0
    const int ty1 = max(i1u, 0);
    const int ty2 = min(i1u + 1, GRID_G - 1);

    __shared__ uint8_t  s_lut[2][GRID_G * NBINS];   // 2 x 2048 B staging
    __shared__ unsigned s_comb[9 * NBINS];          // fused 4-LUT, 9 col-pairs
    __shared__ float    s_outv[256];                // k -> round-exact k/255.0f

    // stage the two LUT rows (2048 B each) with uint4 copies
    {
        const uint4* lutA = (const uint4*)(g_lut + ((size_t)(bc * GRID_G + ty1) * GRID_G) * NBINS);
        const uint4* lutB = (const uint4*)(g_lut + ((size_t)(bc * GRID_G + ty2) * GRID_G) * NBINS);
        if (tid < 128) ((uint4*)s_lut[0])[tid] = lutA[tid];
        else           ((uint4*)s_lut[1])[tid - 128] = lutB[tid - 128];
    }
    // exact IEEE division table: out value = round(res)/255.0
    s_outv[tid] = __fdiv_rn((float)tid, 255.0f);
    __syncthreads();

    // build fused table: 9 column pairs, thread tid handles bin v = tid
    #pragma unroll
    for (int p = 0; p < 9; p++) {
        int tx1 = max(p - 1, 0);
        int tx2 = min(p, GRID_G - 1);
        unsigned l11 = s_lut[0][tx1 * NBINS + tid];
        unsigned l12 = s_lut[0][tx2 * NBINS + tid];
        unsigned l21 = s_lut[1][tx1 * NBINS + tid];
        unsigned l22 = s_lut[1][tx2 * NBINS + tid];
        s_comb[p * NBINS + tid] = l11 | (l12 << 8) | (l21 << 16) | (l22 << 24);
    }
    __syncthreads();

    const uint8_t* dimg = g_img + (size_t)bc * IMG_PIX + (size_t)y0 * IMG_W;
    float*         o    = out   + (size_t)bc * IMG_PIX + (size_t)y0 * IMG_W;

    #pragma unroll
    for (int it = 0; it < 16; it++) {
        int q  = tid + it * 256;        // u32 (4-pixel) index in band: 0..4095
        int r  = q >> 7;                // row in band 0..31
        int c4 = q & 127;

        // vertical weights: iay = (y+32) & 63 with y = y0 + r
        int iay  = (y0 + r + 32) & 63;
        int wy1i = 64 - iay;

        // 4-pixel groups never straddle a tile-column boundary
        // (boundaries at x == 32 mod 64, group-aligned):
        int x0    = c4 * 4;
        int pair  = (x0 + 32) >> 6;              // 0..8
        int iax0  = (x0 + 32) & 63;              // iax for j=0; +j within group
        const unsigned* comb = &s_comb[pair * NBINS];

        unsigned p = *(const unsigned*)(dimg + (size_t)r * IMG_W + x0);

        float4 res;
        float* rp = (float*)&res;
        #pragma unroll
        for (int j = 0; j < 4; j++) {
            int iax = iax0 + j;                  // <= 63 within a group
            unsigned wA = (unsigned)(64 - iax) | ((unsigned)iax << 8);

            unsigned L = comb[(p >> (8 * j)) & 255];
            int A = __dp4a(L, wA, 0u);           // l11*(64-iax) + l12*iax
            int B = __dp4a(L, wA << 16, 0u);     // l21*(64-iax) + l22*iax
            int N = A * wy1i + B * iay;          // res * 4096, exact

            // round-half-even(N / 4096), result guaranteed in [0,255]
            int k = (N + 2047 + ((N >> 12) & 1)) >> 12;
            rp[j] = s_outv[k];
        }
        *(float4*)(o + (size_t)r * IMG_W + x0) = res;
    }
}

// ---------------------------------------------------------------------------
extern "C" void kernel_launch(void* const* d_in, const int* in_sizes, int n_in,
                              void* d_out, int out_size)
{
    const float* x   = (const float*)d_in[0];
    float*       out = (float*)d_out;
    (void)in_sizes; (void)n_in; (void)out_size;

    clahe_hist_lut_kernel<<<N_TILES, 256>>>(x);
    clahe_apply_kernel<<<N_IMG * 16, 256>>>(out);
}

// round 3
// speedup vs baseline: 1.3275x; 1.0280x over previous
#include <cuda_runtime.h>
#include <stdint.h>

// Problem constants (fixed shapes from reference): x = (32, 3, 512, 512) f32.
// 96 images, 8x8 tile grid, tiles of 64x64 (area 4096), 256 bins, clip=32.
#define N_IMG      96
#define IMG_H      512
#define IMG_W      512
#define IMG_PIX    (IMG_H * IMG_W)          // 262144
#define GRID_G     8
#define TILE_H     64
#define TILE_W     64
#define TILE_AREA  (TILE_H * TILE_W)        // 4096
#define NBINS      256
#define CLIP_V     32
#define N_TILES    (N_IMG * GRID_G * GRID_G) // 6144

// Scratch: quantized u8 image + per-tile LUTs (u8). __device__ globals (no alloc).
__device__ uint8_t g_img[(size_t)N_IMG * IMG_PIX];        // 24 MiB
__device__ uint8_t g_lut[(size_t)N_TILES * NBINS];        // 1.5 MiB

// ---------------------------------------------------------------------------
// Kernel 1: per-tile histogram -> clip -> redistribute -> cdf -> LUT,
// and quantize the image to u8 scratch on the way through.
// One block (256 threads) per tile. Two shared sub-histograms (even/odd warp)
// to halve shared-atomic contention.
// ---------------------------------------------------------------------------
__global__ void __launch_bounds__(256)
clahe_hist_lut_kernel(const float* __restrict__ x)
{
    const int tid     = threadIdx.x;        // 0..255, also "my bin"
    const int tile_id = blockIdx.x;         // 0..6143
    const int bc      = tile_id >> 6;       // image index
    const int t       = tile_id & 63;
    const int gy      = t >> 3;
    const int gx      = t & 7;

    __shared__ int s_hist[2 * NBINS];
    __shared__ int s_excess;
    __shared__ int s_warp[8];

    s_hist[tid] = 0;
    s_hist[tid + NBINS] = 0;
    if (tid == 0) s_excess = 0;
    __syncthreads();

    const float* img  = x + (size_t)bc * IMG_PIX;
    uint8_t*     dimg = g_img + (size_t)bc * IMG_PIX;

    const int row0  = gy * TILE_H;
    const int col0  = gx * TILE_W;
    int* myhist = s_hist + ((tid >> 5) & 1) * NBINS;   // even/odd warp split

    #pragma unroll
    for (int i = 0; i < 4; i++) {
        int q  = tid + i * 256;             // float4 index within tile: 0..1023
        int r  = q >> 4;                    // tile row (16 float4 per 64-px row)
        int c4 = q & 15;
        size_t off = (size_t)(row0 + r) * IMG_W + col0 + c4 * 4;
        float4 v = *(const float4*)(img + off);
        // match jnp.round (round-half-even) of clip(x,0,1)*255
        unsigned p0 = (unsigned)rintf(__saturatef(v.x) * 255.0f);
        unsigned p1 = (unsigned)rintf(__saturatef(v.y) * 255.0f);
        unsigned p2 = (unsigned)rintf(__saturatef(v.z) * 255.0f);
        unsigned p3 = (unsigned)rintf(__saturatef(v.w) * 255.0f);
        atomicAdd(&myhist[p0], 1);
        atomicAdd(&myhist[p1], 1);
        atomicAdd(&myhist[p2], 1);
        atomicAdd(&myhist[p3], 1);
        unsigned packed = p0 | (p1 << 8) | (p2 << 16) | (p3 << 24);
        *(unsigned*)(dimg + off) = packed;
    }
    __syncthreads();

    // clip + excess reduction
    int h       = s_hist[tid] + s_hist[tid + NBINS];
    int clipped = min(h, CLIP_V);
    int over    = h - clipped;
    #pragma unroll
    for (int o = 16; o > 0; o >>= 1)
        over += __shfl_down_sync(0xffffffffu, over, o);
    if ((tid & 31) == 0) atomicAdd(&s_excess, over);
    __syncthreads();

    const int excess    = s_excess;
    const int batch_add = excess >> 8;           // excess / 256
    const int residual  = excess & 255;          // excess % 256
    const int step      = max(256 / max(residual, 1), 1);
    const int extra     = ((tid % step) == 0 && (tid / step) < residual) ? 1 : 0;
    int v = clipped + batch_add + extra;

    // inclusive scan over 256 bins (warp scan + warp-sum scan)
    const int lane = tid & 31, wid = tid >> 5;
    int sv = v;
    #pragma unroll
    for (int o = 1; o < 32; o <<= 1) {
        int n = __shfl_up_sync(0xffffffffu, sv, o);
        if (lane >= o) sv += n;
    }
    if (lane == 31) s_warp[wid] = sv;
    __syncthreads();
    if (wid == 0 && lane < 8) {
        int w = s_warp[lane];
        #pragma unroll
        for (int o = 1; o < 8; o <<= 1) {
            int n = __shfl_up_sync(0x000000ffu, w, o);
            if (lane >= o) w += n;
        }
        s_warp[lane] = w;
    }
    __syncthreads();
    int cdf = sv + (wid ? s_warp[wid - 1] : 0);   // 1..4096

    // lut = clip(round(cdf * 255/4096), 0, 255); exact in f32, rintf = half-even
    float lf = rintf((float)cdf * (255.0f / 4096.0f));
    int   li = min(max((int)lf, 0), 255);
    g_lut[(size_t)tile_id * NBINS + tid] = (uint8_t)li;
}

// ---------------------------------------------------------------------------
// Kernel 2: apply LUTs with bilinear tile interpolation.
// One block (256 threads) per 32-row band of one image (16 bands/img).
// Fused 4-way LUT: s_comb[pair][v] = l11 | l12<<8 | l21<<16 | l22<<24 for the
// 9 distinct tile-column pairs -> ONE u32 LDS gather per pixel, exact integer
// DP4A bilinear, then k * (1/255) (<= 1 ulp vs exact division; tol is 1e-3).
// ---------------------------------------------------------------------------
__global__ void __launch_bounds__(256)
clahe_apply_kernel(float* __restrict__ out)
{
    const int tid  = threadIdx.x;
    const int blk  = blockIdx.x;        // 0 .. 96*16-1
    const int bc   = blk >> 4;
    const int band = blk & 15;
    const int y0   = band * 32;

    // tile-row indices for this band (i1 unclamped first, like reference)
    const int i1u = (band - 1) >> 1;            // floor((band-1)/2), -1 at band 0
    const int ty1 = max(i1u, 0);
    const int ty2 = min(i1u + 1, GRID_G - 1);

    __shared__ uint8_t  s_lut[2][GRID_G * NBINS];   // 2 x 2048 B staging
    __shared__ unsigned s_comb[9 * NBINS];          // fused 4-LUT, 9 col-pairs

    // stage the two LUT rows (2048 B each) with uint4 copies
    {
        const uint4* lutA = (const uint4*)(g_lut + ((size_t)(bc * GRID_G + ty1) * GRID_G) * NBINS);
        const uint4* lutB = (const uint4*)(g_lut + ((size_t)(bc * GRID_G + ty2) * GRID_G) * NBINS);
        if (tid < 128) ((uint4*)s_lut[0])[tid] = lutA[tid];
        else           ((uint4*)s_lut[1])[tid - 128] = lutB[tid - 128];
    }
    __syncthreads();

    // build fused table: 9 column pairs, thread tid handles bin v = tid
    #pragma unroll
    for (int p = 0; p < 9; p++) {
        int tx1 = max(p - 1, 0);
        int tx2 = min(p, GRID_G - 1);
        unsigned l11 = s_lut[0][tx1 * NBINS + tid];
        unsigned l12 = s_lut[0][tx2 * NBINS + tid];
        unsigned l21 = s_lut[1][tx1 * NBINS + tid];
        unsigned l22 = s_lut[1][tx2 * NBINS + tid];
        s_comb[p * NBINS + tid] = l11 | (l12 << 8) | (l21 << 16) | (l22 << 24);
    }
    __syncthreads();

    const uint8_t* dimg = g_img + (size_t)bc * IMG_PIX + (size_t)y0 * IMG_W;
    float*         o    = out   + (size_t)bc * IMG_PIX + (size_t)y0 * IMG_W;

    #pragma unroll
    for (int it = 0; it < 16; it++) {
        int q  = tid + it * 256;        // u32 (4-pixel) index in band: 0..4095
        int r  = q >> 7;                // row in band 0..31
        int c4 = q & 127;

        // vertical weights: iay = (y+32) & 63 with y = y0 + r
        int iay  = (y0 + r + 32) & 63;
        int wy1i = 64 - iay;

        // 4-pixel groups never straddle a tile-column boundary
        // (boundaries at x == 32 mod 64, group-aligned):
        int x0    = c4 * 4;
        int pair  = (x0 + 32) >> 6;              // 0..8
        int iax0  = (x0 + 32) & 63;              // iax for j=0; +j within group
        const unsigned* comb = &s_comb[pair * NBINS];

        unsigned p = *(const unsigned*)(dimg + (size_t)r * IMG_W + x0);

        float4 res;
        float* rp = (float*)&res;
        #pragma unroll
        for (int j = 0; j < 4; j++) {
            int iax = iax0 + j;                  // <= 63 within a group
            unsigned wA = (unsigned)(64 - iax) | ((unsigned)iax << 8);

            unsigned L = comb[(p >> (8 * j)) & 255];
            int A = __dp4a(L, wA, 0u);           // l11*(64-iax) + l12*iax
            int B = __dp4a(L, wA << 16, 0u);     // l21*(64-iax) + l22*iax
            int N = A * wy1i + B * iay;          // res * 4096, exact

            // round-half-even(N / 4096), result guaranteed in [0,255]
            int k = (N + 2047 + ((N >> 12) & 1)) >> 12;
            rp[j] = (float)k * (1.0f / 255.0f);  // <= 1 ulp vs __fdiv_rn
        }
        *(float4*)(o + (size_t)r * IMG_W + x0) = res;
    }
}

// ---------------------------------------------------------------------------
extern "C" void kernel_launch(void* const* d_in, const int* in_sizes, int n_in,
                              void* d_out, int out_size)
{
    const float* x   = (const float*)d_in[0];
    float*       out = (float*)d_out;
    (void)in_sizes; (void)n_in; (void)out_size;

    clahe_hist_lut_kernel<<<N_TILES, 256>>>(x);
    clahe_apply_kernel<<<N_IMG * 16, 256>>>(out);
}

// round 4
// speedup vs baseline: 1.3804x; 1.0399x over previous
#include <cuda_runtime.h>
#include <stdint.h>

// Problem constants (fixed shapes from reference): x = (32, 3, 512, 512) f32.
// 96 images, 8x8 tile grid, tiles of 64x64 (area 4096), 256 bins, clip=32.
#define N_IMG      96
#define IMG_H      512
#define IMG_W      512
#define IMG_PIX    (IMG_H * IMG_W)          // 262144
#define GRID_G     8
#define TILE_H     64
#define TILE_W     64
#define TILE_AREA  (TILE_H * TILE_W)        // 4096
#define NBINS      256
#define CLIP_V     32
#define N_TILES    (N_IMG * GRID_G * GRID_G) // 6144
#define NSUB       8                         // interleaved sub-histograms

// Scratch: quantized u8 image + per-tile LUTs (u8). __device__ globals (no alloc).
__device__ uint8_t g_img[(size_t)N_IMG * IMG_PIX];        // 24 MiB
__device__ uint8_t g_lut[(size_t)N_TILES * NBINS];        // 1.5 MiB

// ---------------------------------------------------------------------------
// Kernel 1: per-tile histogram -> clip -> redistribute -> cdf -> LUT,
// and quantize the image to u8 scratch on the way through.
// One block (256 threads) per tile.
// Histogram uses 8 INTERLEAVED sub-histograms: entry [bin*8 + (lane&7)].
// Bank of an atomic = (8*(bin&3) + sub) & 31 -> the warp's 32 atomics spread
// near-uniformly over all 32 banks (vs bank=bin&31 before, ~3.2 replay
// phases). All 4 float4 loads are issued before any atomic (MLP=4).
// ---------------------------------------------------------------------------
__global__ void __launch_bounds__(256)
clahe_hist_lut_kernel(const float* __restrict__ x)
{
    const int tid     = threadIdx.x;        // 0..255, also "my bin"
    const int tile_id = blockIdx.x;         // 0..6143
    const int bc      = tile_id >> 6;       // image index
    const int t       = tile_id & 63;
    const int gy      = t >> 3;
    const int gx      = t & 7;

    __shared__ int s_hist[NSUB * NBINS];    // 8 KB, interleaved
    __shared__ int s_excess;
    __shared__ int s_warp[8];

    #pragma unroll
    for (int i = 0; i < NSUB; i++) s_hist[tid + i * 256] = 0;
    if (tid == 0) s_excess = 0;
    __syncthreads();

    const float* img  = x + (size_t)bc * IMG_PIX;
    uint8_t*     dimg = g_img + (size_t)bc * IMG_PIX;

    const int row0 = gy * TILE_H;
    const int col0 = gx * TILE_W;
    const int sub  = tid & (NSUB - 1);

    // Batch all 16 pixel loads first (guaranteed MLP = 4 x float4)
    float4 v[4];
    size_t offs[4];
    #pragma unroll
    for (int i = 0; i < 4; i++) {
        int q  = tid + i * 256;             // float4 index within tile: 0..1023
        int r  = q >> 4;                    // tile row (16 float4 per 64-px row)
        int c4 = q & 15;
        offs[i] = (size_t)(row0 + r) * IMG_W + col0 + c4 * 4;
        v[i]    = *(const float4*)(img + offs[i]);
    }
    #pragma unroll
    for (int i = 0; i < 4; i++) {
        // match jnp.round (round-half-even) of clip(x,0,1)*255
        unsigned p0 = (unsigned)rintf(__saturatef(v[i].x) * 255.0f);
        unsigned p1 = (unsigned)rintf(__saturatef(v[i].y) * 255.0f);
        unsigned p2 = (unsigned)rintf(__saturatef(v[i].z) * 255.0f);
        unsigned p3 = (unsigned)rintf(__saturatef(v[i].w) * 255.0f);
        atomicAdd(&s_hist[p0 * NSUB + sub], 1);
        atomicAdd(&s_hist[p1 * NSUB + sub], 1);
        atomicAdd(&s_hist[p2 * NSUB + sub], 1);
        atomicAdd(&s_hist[p3 * NSUB + sub], 1);
        unsigned packed = p0 | (p1 << 8) | (p2 << 16) | (p3 << 24);
        *(unsigned*)(dimg + offs[i]) = packed;
    }
    __syncthreads();

    // merge sub-histograms (8 contiguous ints per bin = 2 x int4)
    int4 ha = ((const int4*)s_hist)[tid * 2 + 0];
    int4 hb = ((const int4*)s_hist)[tid * 2 + 1];
    int h   = ha.x + ha.y + ha.z + ha.w + hb.x + hb.y + hb.z + hb.w;

    // clip + excess reduction
    int clipped = min(h, CLIP_V);
    int over    = h - clipped;
    #pragma unroll
    for (int o = 16; o > 0; o >>= 1)
        over += __shfl_down_sync(0xffffffffu, over, o);
    if ((tid & 31) == 0) atomicAdd(&s_excess, over);
    __syncthreads();

    const int excess    = s_excess;
    const int batch_add = excess >> 8;           // excess / 256
    const int residual  = excess & 255;          // excess % 256
    const int step      = max(256 / max(residual, 1), 1);
    const int extra     = ((tid % step) == 0 && (tid / step) < residual) ? 1 : 0;
    int vv = clipped + batch_add + extra;

    // inclusive scan over 256 bins (warp scan + warp-sum scan)
    const int lane = tid & 31, wid = tid >> 5;
    int sv = vv;
    #pragma unroll
    for (int o = 1; o < 32; o <<= 1) {
        int n = __shfl_up_sync(0xffffffffu, sv, o);
        if (lane >= o) sv += n;
    }
    if (lane == 31) s_warp[wid] = sv;
    __syncthreads();
    if (wid == 0 && lane < 8) {
        int w = s_warp[lane];
        #pragma unroll
        for (int o = 1; o < 8; o <<= 1) {
            int n = __shfl_up_sync(0x000000ffu, w, o);
            if (lane >= o) w += n;
        }
        s_warp[lane] = w;
    }
    __syncthreads();
    int cdf = sv + (wid ? s_warp[wid - 1] : 0);   // 1..4096

    // lut = clip(round(cdf * 255/4096), 0, 255); exact in f32, rintf = half-even
    float lf = rintf((float)cdf * (255.0f / 4096.0f));
    int   li = min(max((int)lf, 0), 255);
    g_lut[(size_t)tile_id * NBINS + tid] = (uint8_t)li;
}

// ---------------------------------------------------------------------------
// Kernel 2: apply LUTs with bilinear tile interpolation.
// One block (256 threads) per 16-row HALF-band (32 half-bands/img, 3072
// blocks -> ~2.6 waves at 8 blocks/SM instead of 1.3 -> smaller tail).
// Each half-band uses one tile-row pair: i1u = (hb-2)>>2 (constant per band).
// Fused 4-way LUT: s_comb[pair][v] = l11 | l12<<8 | l21<<16 | l22<<24 for the
// 9 distinct tile-column pairs -> ONE u32 LDS gather per pixel, exact integer
// DP4A bilinear, then k * (1/255) (<= 1 ulp vs exact division; tol is 1e-3).
// ---------------------------------------------------------------------------
__global__ void __launch_bounds__(256)
clahe_apply_kernel(float* __restrict__ out)
{
    const int tid  = threadIdx.x;
    const int blk  = blockIdx.x;        // 0 .. 96*32-1
    const int bc   = blk >> 5;
    const int hb   = blk & 31;          // half-band index (16 rows each)
    const int y0   = hb * 16;

    // tile-row indices for this half-band (constant; boundaries only at band starts)
    const int i1u = (hb - 2) >> 2;              // floor((y-32)/64) for all y in band
    const int ty1 = max(i1u, 0);
    const int ty2 = min(i1u + 1, GRID_G - 1);

    __shared__ uint8_t  s_lut[2][GRID_G * NBINS];   // 2 x 2048 B staging
    __shared__ unsigned s_comb[9 * NBINS];          // fused 4-LUT, 9 col-pairs

    // stage the two LUT rows (2048 B each) with uint4 copies
    {
        const uint4* lutA = (const uint4*)(g_lut + ((size_t)(bc * GRID_G + ty1) * GRID_G) * NBINS);
        const uint4* lutB = (const uint4*)(g_lut + ((size_t)(bc * GRID_G + ty2) * GRID_G) * NBINS);
        if (tid < 128) ((uint4*)s_lut[0])[tid] = lutA[tid];
        else           ((uint4*)s_lut[1])[tid - 128] = lutB[tid - 128];
    }
    __syncthreads();

    // build fused table: 9 column pairs, thread tid handles bin v = tid
    #pragma unroll
    for (int p = 0; p < 9; p++) {
        int tx1 = max(p - 1, 0);
        int tx2 = min(p, GRID_G - 1);
        unsigned l11 = s_lut[0][tx1 * NBINS + tid];
        unsigned l12 = s_lut[0][tx2 * NBINS + tid];
        unsigned l21 = s_lut[1][tx1 * NBINS + tid];
        unsigned l22 = s_lut[1][tx2 * NBINS + tid];
        s_comb[p * NBINS + tid] = l11 | (l12 << 8) | (l21 << 16) | (l22 << 24);
    }
    __syncthreads();

    const uint8_t* dimg = g_img + (size_t)bc * IMG_PIX + (size_t)y0 * IMG_W;
    float*         o    = out   + (size_t)bc * IMG_PIX + (size_t)y0 * IMG_W;

    #pragma unroll
    for (int it = 0; it < 8; it++) {
        int q  = tid + it * 256;        // u32 (4-pixel) index in band: 0..2047
        int r  = q >> 7;                // row in band 0..15
        int c4 = q & 127;

        // vertical weights: iay = (y+32) & 63 with y = y0 + r
        int iay  = (y0 + r + 32) & 63;
        int wy1i = 64 - iay;

        // 4-pixel groups never straddle a tile-column boundary
        // (boundaries at x == 32 mod 64, group-aligned):
        int x0    = c4 * 4;
        int pair  = (x0 + 32) >> 6;              // 0..8
        int iax0  = (x0 + 32) & 63;              // iax for j=0; +j within group
        const unsigned* comb = &s_comb[pair * NBINS];

        unsigned p = *(const unsigned*)(dimg + (size_t)r * IMG_W + x0);

        float4 res;
        float* rp = (float*)&res;
        #pragma unroll
        for (int j = 0; j < 4; j++) {
            int iax = iax0 + j;                  // <= 63 within a group
            unsigned wA = (unsigned)(64 - iax) | ((unsigned)iax << 8);

            unsigned L = comb[(p >> (8 * j)) & 255];
            int A = __dp4a(L, wA, 0u);           // l11*(64-iax) + l12*iax
            int B = __dp4a(L, wA << 16, 0u);     // l21*(64-iax) + l22*iax
            int N = A * wy1i + B * iay;          // res * 4096, exact

            // round-half-even(N / 4096), result guaranteed in [0,255]
            int k = (N + 2047 + ((N >> 12) & 1)) >> 12;
            rp[j] = (float)k * (1.0f / 255.0f);  // <= 1 ulp vs __fdiv_rn
        }
        *(float4*)(o + (size_t)r * IMG_W + x0) = res;
    }
}

// ---------------------------------------------------------------------------
extern "C" void kernel_launch(void* const* d_in, const int* in_sizes, int n_in,
                              void* d_out, int out_size)
{
    const float* x   = (const float*)d_in[0];
    float*       out = (float*)d_out;
    (void)in_sizes; (void)n_in; (void)out_size;

    clahe_hist_lut_kernel<<<N_TILES, 256>>>(x);
    clahe_apply_kernel<<<N_IMG * 32, 256>>>(out);
}